// round 14
// baseline (speedup 1.0000x reference)
#include <cuda_runtime.h>
#include <cuda_fp16.h>
#include <cstdint>
#include <math.h>

// Problem dims (fixed by the dataset)
constexpr int S  = 8192;   // B*T tokens
constexpr int D  = 2048;   // model dim
constexpr int H  = 2048;   // expert hidden
constexpr int E  = 8;      // experts
constexpr int KK = 2;      // top-k
constexpr int CAP = 2048;  // per-expert capacity
constexpr int B  = 4;
constexpr int T  = 2048;

// GEMM tiling (HMMA fp16: CTA 128x256, 8 warps = 2M x 4N, warp 64x64)
constexpr int MT = 128;
constexpr int NTT = 256;
constexpr int KTILE = 64;            // k elements per stage (128-B rows)
constexpr int STAGES = 4;
constexpr int NK = D / KTILE;        // 32 iterations
constexpr int NTILES = H / NTT;      // 8 N-tiles per expert row
constexpr int ASTAGE = MT * 128;     // 16384 B
constexpr int BSTAGE = NTT * 128;    // 32768 B
constexpr int SMEM_FFN = STAGES * (ASTAGE + BSTAGE);  // 196608 B

// k_prep block dispatch
constexpr int PREP_CONV = (H / 64) * (D / 64) * E;   // 8192 convw1 blocks
constexpr int PREP_W2   = (E * H) / 8;               // 2048 w2-rowsum blocks
constexpr int PREP_TOT  = PREP_CONV + PREP_W2 + 1;   // +1 b2 block

// ---------------- device scratch (no allocations allowed) ----------------
__device__ int   g_eid[KK * S];
__device__ float g_wgt[KK * S];
__device__ int   g_src[E * CAP];       // slot -> source token (-1 = empty)
__device__ int   g_tokslot[KK * S];    // (k,s) -> slot index or -1
__device__ float g_w2sum[E * H];
__device__ float g_b2sum[E];
__device__ float g_part[(size_t)E * CAP * NTILES];
__device__ __half g_ah[(size_t)E * CAP * D];    // gathered tokens (fp16)
__device__ __half g_w1h[(size_t)E * H * D];     // w1^T [E][H][D] (fp16)

// ---------------- host-side stream/event (created at program load) ------
static cudaStream_t g_side_stream;
static cudaEvent_t  g_ev_fork, g_ev_join;
namespace {
struct StreamInit {
    StreamInit() {
        cudaStreamCreateWithFlags(&g_side_stream, cudaStreamNonBlocking);
        cudaEventCreateWithFlags(&g_ev_fork, cudaEventDisableTiming);
        cudaEventCreateWithFlags(&g_ev_join, cudaEventDisableTiming);
    }
};
StreamInit g_stream_init;
}  // namespace

// ---------------- PTX helpers (baseline ISA: sm_80-class) ---------------
__device__ __forceinline__ uint32_t s2u(const void* p) {
    return (uint32_t)__cvta_generic_to_shared(p);
}
__device__ __forceinline__ void cpa16(uint32_t s, const void* g) {
    asm volatile("cp.async.cg.shared.global [%0], [%1], 16;" :: "r"(s), "l"(g));
}
__device__ __forceinline__ void cp_commit() {
    asm volatile("cp.async.commit_group;" ::: "memory");
}
template <int N>
__device__ __forceinline__ void cp_wait() {
    asm volatile("cp.async.wait_group %0;" :: "n"(N) : "memory");
}
__device__ __forceinline__ void ldsm4(uint32_t* r, uint32_t addr) {
    asm volatile("ldmatrix.sync.aligned.m8n8.x4.shared.b16 {%0,%1,%2,%3}, [%4];"
                 : "=r"(r[0]), "=r"(r[1]), "=r"(r[2]), "=r"(r[3]) : "r"(addr));
}
__device__ __forceinline__ void mma16816(float* c, const uint32_t* a,
                                         uint32_t b0, uint32_t b1) {
    asm volatile(
        "mma.sync.aligned.m16n8k16.row.col.f32.f16.f16.f32 "
        "{%0,%1,%2,%3}, {%4,%5,%6,%7}, {%8,%9}, {%0,%1,%2,%3};"
        : "+f"(c[0]), "+f"(c[1]), "+f"(c[2]), "+f"(c[3])
        : "r"(a[0]), "r"(a[1]), "r"(a[2]), "r"(a[3]), "r"(b0), "r"(b1));
}
__device__ __forceinline__ uint32_t swz128(uint32_t off) {
    return off ^ ((off >> 3) & 0x70);
}

// ---------------- K0: merged weight prep --------------------------------
__global__ void k_prep(const float* __restrict__ w1,
                       const float* __restrict__ w2,
                       const float* __restrict__ b2) {
    __shared__ float ts[64][65];
    const int bi = blockIdx.x;
    const int t  = threadIdx.x;          // 256
    if (bi < PREP_CONV) {
        const int e   = bi >> 10;
        const int rem = bi & 1023;
        const int h0  = (rem & 31) * 64;
        const int d0  = (rem >> 5) * 64;
        const int c4  = (t & 15) * 4;
        const int r   = t >> 4;          // 0..15
        #pragma unroll
        for (int j = 0; j < 4; j++) {
            int dr = r + 16 * j;
            float4 v = *(const float4*)(w1 + ((size_t)e * D + d0 + dr) * H + h0 + c4);
            ts[dr][c4 + 0] = v.x;
            ts[dr][c4 + 1] = v.y;
            ts[dr][c4 + 2] = v.z;
            ts[dr][c4 + 3] = v.w;
        }
        __syncthreads();
        #pragma unroll
        for (int j = 0; j < 4; j++) {
            int hr = r + 16 * j;
            union { __half2 h[2]; uint2 u; } p;
            p.h[0] = __floats2half2_rn(ts[c4 + 0][hr], ts[c4 + 1][hr]);
            p.h[1] = __floats2half2_rn(ts[c4 + 2][hr], ts[c4 + 3][hr]);
            *(uint2*)(g_w1h + ((size_t)e * H + h0 + hr) * D + d0 + c4) = p.u;
        }
    } else if (bi < PREP_CONV + PREP_W2) {
        const int gw   = (bi - PREP_CONV) * 8 + (t >> 5);
        const int lane = t & 31;
        const float* row = w2 + (size_t)gw * D;
        float s = 0.f;
        #pragma unroll
        for (int d = lane * 4; d < D; d += 128) {
            float4 v = *(const float4*)(row + d);
            s += v.x + v.y + v.z + v.w;
        }
        #pragma unroll
        for (int o = 16; o; o >>= 1) s += __shfl_xor_sync(0xffffffffu, s, o);
        if (lane == 0) g_w2sum[gw] = s;
    } else {
        const int wid  = t >> 5;         // row = expert
        const int lane = t & 31;
        const float* row = b2 + (size_t)wid * D;
        float s = 0.f;
        #pragma unroll
        for (int d = lane * 4; d < D; d += 128) {
            float4 v = *(const float4*)(row + d);
            s += v.x + v.y + v.z + v.w;
        }
        #pragma unroll
        for (int o = 16; o; o >>= 1) s += __shfl_xor_sync(0xffffffffu, s, o);
        if (lane == 0) g_b2sum[wid] = s;
    }
}

// ---------------- K1: gating (top-2 of softmax(x@wg), normalized) ------
__global__ void k_gate(const float* __restrict__ x, const float* __restrict__ wg) {
    extern __shared__ float swg[];   // [8][2048] = 64 KB
    const int t = threadIdx.x;       // 512
    for (int i = t; i < D * E; i += 512) {
        int d = i >> 3, e = i & 7;
        swg[e * D + d] = wg[i];
    }
    __syncthreads();

    const int wid  = t >> 5;         // 0..15
    const int lane = t & 31;
    const int tok0 = blockIdx.x * 32 + wid * 2;
    const float* xr0 = x + (size_t)tok0 * D;
    const float* xr1 = xr0 + D;

    float a0[8] = {0, 0, 0, 0, 0, 0, 0, 0};
    float a1[8] = {0, 0, 0, 0, 0, 0, 0, 0};
    for (int d = lane * 4; d < D; d += 128) {
        float4 xv0 = *(const float4*)(xr0 + d);
        float4 xv1 = *(const float4*)(xr1 + d);
        #pragma unroll
        for (int e = 0; e < 8; e++) {
            float4 w = *(const float4*)&swg[e * D + d];
            a0[e] = fmaf(xv0.x, w.x, a0[e]);
            a0[e] = fmaf(xv0.y, w.y, a0[e]);
            a0[e] = fmaf(xv0.z, w.z, a0[e]);
            a0[e] = fmaf(xv0.w, w.w, a0[e]);
            a1[e] = fmaf(xv1.x, w.x, a1[e]);
            a1[e] = fmaf(xv1.y, w.y, a1[e]);
            a1[e] = fmaf(xv1.z, w.z, a1[e]);
            a1[e] = fmaf(xv1.w, w.w, a1[e]);
        }
    }
    #pragma unroll
    for (int ee = 0; ee < 8; ee++) {
        #pragma unroll
        for (int o = 16; o; o >>= 1) {
            a0[ee] += __shfl_xor_sync(0xffffffffu, a0[ee], o);
            a1[ee] += __shfl_xor_sync(0xffffffffu, a1[ee], o);
        }
    }
    if (lane == 0) {
        #pragma unroll
        for (int tk = 0; tk < 2; tk++) {
            const float* acc = tk ? a1 : a0;
            const int tok = tok0 + tk;
            int i0 = 0; float v0 = acc[0];
            #pragma unroll
            for (int ee = 1; ee < 8; ee++)
                if (acc[ee] > v0) { v0 = acc[ee]; i0 = ee; }
            int i1 = -1; float v1 = -INFINITY;
            #pragma unroll
            for (int ee = 0; ee < 8; ee++)
                if (ee != i0 && acc[ee] > v1) { v1 = acc[ee]; i1 = ee; }
            float w0 = 1.f / (1.f + expf(v1 - v0));
            g_eid[tok]     = i0;
            g_eid[S + tok] = i1;
            g_wgt[tok]     = w0;
            g_wgt[S + tok] = 1.f - w0;
        }
    }
}

// ---------------- K2: capacity-aware slot assignment (one block) -------
__global__ void k_assign() {
    __shared__ int hist[1024][8];
    const int t = threadIdx.x;
    for (int i = t; i < E * CAP; i += 1024) g_src[i] = -1;
    int h[8] = {0, 0, 0, 0, 0, 0, 0, 0};
    const int base = t * 16;
    #pragma unroll
    for (int j = 0; j < 16; j++) h[g_eid[base + j]]++;
    #pragma unroll
    for (int ee = 0; ee < 8; ee++) hist[t][ee] = h[ee];
    __syncthreads();
    const int wid = t >> 5, lane = t & 31;
    if (wid < 8) {
        int p = 0;
        #pragma unroll
        for (int j = 0; j < 32; j++) p += hist[lane * 32 + j][wid];
        int ex = p;
        #pragma unroll
        for (int o = 1; o < 32; o <<= 1) {
            int v = __shfl_up_sync(0xffffffffu, ex, o);
            if (lane >= o) ex += v;
        }
        ex -= p;  // exclusive
        int run = ex;
        #pragma unroll
        for (int j = 0; j < 32; j++) {
            int v = hist[lane * 32 + j][wid];
            hist[lane * 32 + j][wid] = run;
            run += v;
        }
    }
    __syncthreads();
    int cnt[8];
    #pragma unroll
    for (int ee = 0; ee < 8; ee++) cnt[ee] = hist[t][ee];
    #pragma unroll
    for (int j = 0; j < 16; j++) {
        int n = base + j;
        int e = g_eid[n];
        int loc = cnt[e]++;
        if (loc < CAP) {
            g_src[e * CAP + loc] = n & (S - 1);
            g_tokslot[n] = e * CAP + loc;
        } else {
            g_tokslot[n] = -1;
        }
    }
}

// ---------------- K2b: gather tokens into fp16 A ------------------------
__global__ void k_gather(const float* __restrict__ x) {
    const int row  = blockIdx.x * 4 + (threadIdx.x >> 6);  // grid = E*CAP/4
    const int sub  = threadIdx.x & 63;
    const int stok = g_src[row];
    __half* oh = g_ah + (size_t)row * D;
    if (stok < 0) {
        const uint4 z = make_uint4(0u, 0u, 0u, 0u);
        #pragma unroll
        for (int j = 0; j < 4; j++)
            *(uint4*)(oh + sub * 8 + j * 512) = z;
        return;
    }
    const float* xr = x + (size_t)stok * D + sub * 8;
    float4 v[4][2];
    #pragma unroll
    for (int j = 0; j < 4; j++) {
        v[j][0] = *(const float4*)(xr + j * 512);
        v[j][1] = *(const float4*)(xr + j * 512 + 4);
    }
    #pragma unroll
    for (int j = 0; j < 4; j++) {
        union { __half2 h[4]; uint4 u; } p;
        p.h[0] = __floats2half2_rn(v[j][0].x, v[j][0].y);
        p.h[1] = __floats2half2_rn(v[j][0].z, v[j][0].w);
        p.h[2] = __floats2half2_rn(v[j][1].x, v[j][1].y);
        p.h[3] = __floats2half2_rn(v[j][1].z, v[j][1].w);
        *(uint4*)(oh + sub * 8 + j * 512) = p.u;
    }
}

// ---------------- K3: fp16 HMMA expert GEMM + fused epilogue ------------
// grid = (H/256, CAP/128, E). CTA 128x256, warp tile 64x64, 4 stages,
// 192 KB smem, 1 CTA/SM. 128-B SW128 rows, conflict-free ldmatrix.
__global__ void __launch_bounds__(256, 1)
k_ffn_mma(const float* __restrict__ b1) {
    extern __shared__ char smem[];
    const uint32_t sA = s2u(smem);
    const uint32_t sB = sA + STAGES * ASTAGE;
    const int e  = blockIdx.z;
    const int m0 = blockIdx.y * MT;
    const int n0 = blockIdx.x * NTT;
    const int t  = threadIdx.x;
    const int lane = t & 31;
    const int wid  = t >> 5;
    const int warpM = wid >> 2;       // 0..1  (64 rows each)
    const int warpN = wid & 3;        // 0..3  (64 cols each)

    const char* pA = (const char*)(g_ah + (size_t)(e * CAP + m0) * D);
    const char* pB = (const char*)(g_w1h + ((size_t)e * H + n0) * D);
    const size_t RS = (size_t)D * 2;  // 4096 B global row stride

    // per-thread load coords: A 1024 + B 2048 chunks of 16B per stage
    auto load_stage = [&](int st, int buf) {
        const size_t kb = (size_t)st * (KTILE * 2);
        #pragma unroll
        for (int j = 0; j < 4; j++) {
            int idx = t + 256 * j;
            int row = idx >> 3, c = idx & 7;
            uint32_t so = swz128((uint32_t)(row * 128 + c * 16));
            cpa16(sA + buf * ASTAGE + so, pA + (size_t)row * RS + kb + c * 16);
        }
        #pragma unroll
        for (int j = 0; j < 8; j++) {
            int idx = t + 256 * j;
            int row = idx >> 3, c = idx & 7;
            uint32_t so = swz128((uint32_t)(row * 128 + c * 16));
            cpa16(sB + buf * BSTAGE + so, pB + (size_t)row * RS + kb + c * 16);
        }
    };

    float acc[4][8][4];
    #pragma unroll
    for (int i = 0; i < 4; i++)
        #pragma unroll
        for (int j = 0; j < 8; j++)
            #pragma unroll
            for (int q = 0; q < 4; q++) acc[i][j][q] = 0.f;

    // ldmatrix per-lane base offsets (unswizzled, 128-B rows)
    const uint32_t aBase = (uint32_t)((warpM * 64 + (lane & 15)) * 128 +
                                      ((lane >> 4) << 4));
    const int brow = warpN * 64 + (lane & 7) + ((lane & 16) >> 1);
    const uint32_t bBase = (uint32_t)(brow * 128 + ((lane & 8) << 1));

    // prologue: stages 0..STAGES-2
    #pragma unroll
    for (int st = 0; st < STAGES - 1; st++) {
        load_stage(st, st);
        cp_commit();
    }

    #pragma unroll 1
    for (int it = 0; it < NK; it++) {
        cp_wait<STAGES - 2>();
        __syncthreads();
        if (it + STAGES - 1 < NK) {
            int st = it + STAGES - 1;
            load_stage(st, st % STAGES);
        }
        cp_commit();

        const int buf = it % STAGES;
        const uint32_t abuf = sA + buf * ASTAGE;
        const uint32_t bbuf = sB + buf * BSTAGE;
        #pragma unroll
        for (int s = 0; s < 4; s++) {
            uint32_t a[4][4], b[4][4];
            #pragma unroll
            for (int mt = 0; mt < 4; mt++)
                ldsm4(a[mt], abuf + swz128(aBase + mt * 2048 + s * 32));
            #pragma unroll
            for (int np = 0; np < 4; np++)
                ldsm4(b[np], bbuf + swz128(bBase + np * 2048 + s * 32));
            #pragma unroll
            for (int mt = 0; mt < 4; mt++)
                #pragma unroll
                for (int nt = 0; nt < 8; nt++) {
                    const int np = nt >> 1, o = (nt & 1) * 2;
                    mma16816(acc[mt][nt], a[mt], b[np][o], b[np][o + 1]);
                }
        }
    }

    // ---- epilogue: relu(acc + b1) . w2sum, reduce over 256 N ----
    __syncthreads();                       // all loads retired; reuse smem
    float* red = (float*)smem;             // [128][4]
    const int g  = lane >> 2;
    const int t4 = lane & 3;
    const float* b1p = b1 + (size_t)e * H + n0;
    const float* wp  = g_w2sum + (size_t)e * H + n0;
    #pragma unroll
    for (int mt = 0; mt < 4; mt++) {
        float sAcc = 0.f, sBcc = 0.f;
        #pragma unroll
        for (int nt = 0; nt < 8; nt++) {
            int ni = warpN * 64 + nt * 8 + t4 * 2;
            float bb0 = __ldg(b1p + ni),     ww0 = __ldg(wp + ni);
            float bb1 = __ldg(b1p + ni + 1), ww1 = __ldg(wp + ni + 1);
            sAcc += fmaxf(acc[mt][nt][0] + bb0, 0.f) * ww0 +
                    fmaxf(acc[mt][nt][1] + bb1, 0.f) * ww1;
            sBcc += fmaxf(acc[mt][nt][2] + bb0, 0.f) * ww0 +
                    fmaxf(acc[mt][nt][3] + bb1, 0.f) * ww1;
        }
        sAcc += __shfl_xor_sync(0xffffffffu, sAcc, 1);
        sAcc += __shfl_xor_sync(0xffffffffu, sAcc, 2);
        sBcc += __shfl_xor_sync(0xffffffffu, sBcc, 1);
        sBcc += __shfl_xor_sync(0xffffffffu, sBcc, 2);
        if (t4 == 0) {
            int r = warpM * 64 + mt * 16 + g;
            red[r * 4 + warpN]       = sAcc;
            red[(r + 8) * 4 + warpN] = sBcc;
        }
    }
    __syncthreads();
    if (t < 128) {
        float v = red[t * 4] + red[t * 4 + 1] + red[t * 4 + 2] + red[t * 4 + 3];
        g_part[(size_t)(e * CAP + m0 + t) * NTILES + blockIdx.x] = v;
    }
}

// ---------------- K4: fused combine + log_softmax -----------------------
__global__ void k_out(float* __restrict__ out) {
    __shared__ float sh[1024];
    const int b = blockIdx.x;
    const int t = threadIdx.x;
    float v[2];
    #pragma unroll
    for (int half = 0; half < 2; half++) {
        const int s = b * T + t + half * 1024;
        float l = 0.f;
        #pragma unroll
        for (int k = 0; k < KK; k++) {
            int slot = g_tokslot[k * S + s];
            if (slot >= 0) {
                const float4* p = (const float4*)(g_part + (size_t)slot * NTILES);
                float4 c0 = p[0], c1 = p[1];
                float c = c0.x + c0.y + c0.z + c0.w + c1.x + c1.y + c1.z + c1.w;
                l += g_wgt[k * S + s] * (c + g_b2sum[g_eid[k * S + s]]);
            }
        }
        v[half] = l;
    }
    sh[t] = fmaxf(v[0], v[1]);
    __syncthreads();
    for (int o = 512; o; o >>= 1) {
        if (t < o) sh[t] = fmaxf(sh[t], sh[t + o]);
        __syncthreads();
    }
    const float mx = sh[0];
    __syncthreads();
    sh[t] = expf(v[0] - mx) + expf(v[1] - mx);
    __syncthreads();
    for (int o = 512; o; o >>= 1) {
        if (t < o) sh[t] += sh[t + o];
        __syncthreads();
    }
    const float lse = logf(sh[0]) + mx;
    out[(size_t)b * T + t]        = v[0] - lse;
    out[(size_t)b * T + t + 1024] = v[1] - lse;
}

// ---------------- launch ------------------------------------------------
extern "C" void kernel_launch(void* const* d_in, const int* in_sizes, int n_in,
                              void* d_out, int out_size) {
    const float* x  = (const float*)d_in[0];   // [B,T,D]
    const float* wg = (const float*)d_in[1];   // [D,E]
    const float* w1 = (const float*)d_in[2];   // [E,D,H]
    const float* b1 = (const float*)d_in[3];   // [E,H]
    const float* w2 = (const float*)d_in[4];   // [E,H,D]
    const float* b2 = (const float*)d_in[5];   // [E,D]
    float* out = (float*)d_out;                // [B,T]
    (void)in_sizes; (void)n_in; (void)out_size;

    cudaFuncSetAttribute(k_ffn_mma,
                         cudaFuncAttributeMaxDynamicSharedMemorySize, SMEM_FFN);
    cudaFuncSetAttribute(k_gate,
                         cudaFuncAttributeMaxDynamicSharedMemorySize, D * E * 4);

    // fork: weight prep on the side stream, overlapped with token branch
    cudaEventRecord(g_ev_fork, 0);
    cudaStreamWaitEvent(g_side_stream, g_ev_fork, 0);
    k_prep<<<PREP_TOT, 256, 0, g_side_stream>>>(w1, w2, b2);
    cudaEventRecord(g_ev_join, g_side_stream);

    // token branch on the main stream
    k_gate<<<S / 32, 512, D * E * 4>>>(x, wg);
    k_assign<<<1, 1024>>>();
    k_gather<<<(E * CAP) / 4, 256>>>(x);

    // join: GEMM needs both branches
    cudaStreamWaitEvent(0, g_ev_join, 0);
    k_ffn_mma<<<dim3(H / NTT, CAP / MT, E), 256, SMEM_FFN>>>(b1);

    // fused combine + log_softmax
    k_out<<<B, 1024>>>(out);
}

// round 15
// speedup vs baseline: 1.0659x; 1.0659x over previous
#include <cuda_runtime.h>
#include <cuda_fp16.h>
#include <cstdint>
#include <math.h>

// Problem dims (fixed by the dataset)
constexpr int S  = 8192;   // B*T tokens
constexpr int D  = 2048;   // model dim
constexpr int H  = 2048;   // expert hidden
constexpr int E  = 8;      // experts
constexpr int KK = 2;      // top-k
constexpr int CAP = 2048;  // per-expert capacity
constexpr int B  = 4;
constexpr int T  = 2048;

// GEMM tiling (HMMA fp16: CTA 128x128, 8 warps = 2M x 4N, warp 64x32)
constexpr int MT = 128;
constexpr int NTT = 128;
constexpr int KTILE = 64;            // k elements per stage (128-B rows)
constexpr int STAGES = 3;
constexpr int NK = D / KTILE;        // 32 iterations
constexpr int NTILES = H / NTT;      // 16 N-tiles per expert row
constexpr int ASTAGE = MT * 128;     // 16384 B
constexpr int BSTAGE = NTT * 128;    // 16384 B
constexpr int SMEM_FFN = STAGES * (ASTAGE + BSTAGE);  // 98304 B

// k_prep block dispatch
constexpr int PREP_CONV = (H / 64) * (D / 64) * E;   // 8192 convw1 blocks
constexpr int PREP_W2   = (E * H) / 8;               // 2048 w2-rowsum blocks
constexpr int PREP_TOT  = PREP_CONV + PREP_W2 + 1;   // +1 b2 block

// ---------------- device scratch (no allocations allowed) ----------------
__device__ int   g_eid[KK * S];
__device__ float g_wgt[KK * S];
__device__ int   g_src[E * CAP];       // slot -> source token (-1 = empty)
__device__ int   g_tokslot[KK * S];    // (k,s) -> slot index or -1
__device__ float g_w2sum[E * H];
__device__ float g_b2sum[E];
__device__ float g_part[(size_t)E * CAP * NTILES];
// x converted to fp16 (written by k_gate); row S is a never-written zero row
// (device globals are zero-initialized) used for empty capacity slots.
__device__ __half g_xh[(size_t)(S + 1) * D];
__device__ __half g_w1h[(size_t)E * H * D];     // w1^T [E][H][D] (fp16)

// ---------------- host-side stream/event (created at program load) ------
static cudaStream_t g_side_stream;
static cudaEvent_t  g_ev_fork, g_ev_join;
namespace {
struct StreamInit {
    StreamInit() {
        cudaStreamCreateWithFlags(&g_side_stream, cudaStreamNonBlocking);
        cudaEventCreateWithFlags(&g_ev_fork, cudaEventDisableTiming);
        cudaEventCreateWithFlags(&g_ev_join, cudaEventDisableTiming);
    }
};
StreamInit g_stream_init;
}  // namespace

// ---------------- PTX helpers (baseline ISA: sm_80-class) ---------------
__device__ __forceinline__ uint32_t s2u(const void* p) {
    return (uint32_t)__cvta_generic_to_shared(p);
}
__device__ __forceinline__ void cpa16(uint32_t s, const void* g) {
    asm volatile("cp.async.cg.shared.global [%0], [%1], 16;" :: "r"(s), "l"(g));
}
__device__ __forceinline__ void cp_commit() {
    asm volatile("cp.async.commit_group;" ::: "memory");
}
template <int N>
__device__ __forceinline__ void cp_wait() {
    asm volatile("cp.async.wait_group %0;" :: "n"(N) : "memory");
}
__device__ __forceinline__ void ldsm4(uint32_t* r, uint32_t addr) {
    asm volatile("ldmatrix.sync.aligned.m8n8.x4.shared.b16 {%0,%1,%2,%3}, [%4];"
                 : "=r"(r[0]), "=r"(r[1]), "=r"(r[2]), "=r"(r[3]) : "r"(addr));
}
__device__ __forceinline__ void mma16816(float* c, const uint32_t* a,
                                         uint32_t b0, uint32_t b1) {
    asm volatile(
        "mma.sync.aligned.m16n8k16.row.col.f32.f16.f16.f32 "
        "{%0,%1,%2,%3}, {%4,%5,%6,%7}, {%8,%9}, {%0,%1,%2,%3};"
        : "+f"(c[0]), "+f"(c[1]), "+f"(c[2]), "+f"(c[3])
        : "r"(a[0]), "r"(a[1]), "r"(a[2]), "r"(a[3]), "r"(b0), "r"(b1));
}
__device__ __forceinline__ uint32_t swz128(uint32_t off) {
    return off ^ ((off >> 3) & 0x70);
}

// ---------------- K0: merged weight prep --------------------------------
__global__ void k_prep(const float* __restrict__ w1,
                       const float* __restrict__ w2,
                       const float* __restrict__ b2) {
    __shared__ float ts[64][65];
    const int bi = blockIdx.x;
    const int t  = threadIdx.x;          // 256
    if (bi < PREP_CONV) {
        const int e   = bi >> 10;
        const int rem = bi & 1023;
        const int h0  = (rem & 31) * 64;
        const int d0  = (rem >> 5) * 64;
        const int c4  = (t & 15) * 4;
        const int r   = t >> 4;          // 0..15
        #pragma unroll
        for (int j = 0; j < 4; j++) {
            int dr = r + 16 * j;
            float4 v = *(const float4*)(w1 + ((size_t)e * D + d0 + dr) * H + h0 + c4);
            ts[dr][c4 + 0] = v.x;
            ts[dr][c4 + 1] = v.y;
            ts[dr][c4 + 2] = v.z;
            ts[dr][c4 + 3] = v.w;
        }
        __syncthreads();
        #pragma unroll
        for (int j = 0; j < 4; j++) {
            int hr = r + 16 * j;
            union { __half2 h[2]; uint2 u; } p;
            p.h[0] = __floats2half2_rn(ts[c4 + 0][hr], ts[c4 + 1][hr]);
            p.h[1] = __floats2half2_rn(ts[c4 + 2][hr], ts[c4 + 3][hr]);
            *(uint2*)(g_w1h + ((size_t)e * H + h0 + hr) * D + d0 + c4) = p.u;
        }
    } else if (bi < PREP_CONV + PREP_W2) {
        const int gw   = (bi - PREP_CONV) * 8 + (t >> 5);
        const int lane = t & 31;
        const float* row = w2 + (size_t)gw * D;
        float s = 0.f;
        #pragma unroll
        for (int d = lane * 4; d < D; d += 128) {
            float4 v = *(const float4*)(row + d);
            s += v.x + v.y + v.z + v.w;
        }
        #pragma unroll
        for (int o = 16; o; o >>= 1) s += __shfl_xor_sync(0xffffffffu, s, o);
        if (lane == 0) g_w2sum[gw] = s;
    } else {
        const int wid  = t >> 5;         // row = expert
        const int lane = t & 31;
        const float* row = b2 + (size_t)wid * D;
        float s = 0.f;
        #pragma unroll
        for (int d = lane * 4; d < D; d += 128) {
            float4 v = *(const float4*)(row + d);
            s += v.x + v.y + v.z + v.w;
        }
        #pragma unroll
        for (int o = 16; o; o >>= 1) s += __shfl_xor_sync(0xffffffffu, s, o);
        if (lane == 0) g_b2sum[wid] = s;
    }
}

// ---------------- K1: gating + fused x->fp16 conversion -----------------
// 512 threads, 32 tokens per block (16 warps x 2 tokens). While streaming
// x for the gating dot products, also writes the fp16 copy g_xh (the GEMM
// A-loader reads it via slot indirection; no separate gather pass).
__global__ void k_gate(const float* __restrict__ x, const float* __restrict__ wg) {
    extern __shared__ float swg[];   // [8][2048] = 64 KB
    const int t = threadIdx.x;       // 512
    for (int i = t; i < D * E; i += 512) {
        int d = i >> 3, e = i & 7;
        swg[e * D + d] = wg[i];
    }
    __syncthreads();

    const int wid  = t >> 5;         // 0..15
    const int lane = t & 31;
    const int tok0 = blockIdx.x * 32 + wid * 2;
    const float* xr0 = x + (size_t)tok0 * D;
    const float* xr1 = xr0 + D;
    __half* xo0 = g_xh + (size_t)tok0 * D;
    __half* xo1 = xo0 + D;

    float a0[8] = {0, 0, 0, 0, 0, 0, 0, 0};
    float a1[8] = {0, 0, 0, 0, 0, 0, 0, 0};
    for (int d = lane * 4; d < D; d += 128) {
        float4 xv0 = *(const float4*)(xr0 + d);
        float4 xv1 = *(const float4*)(xr1 + d);
        union { __half2 h[2]; uint2 u; } p0, p1;
        p0.h[0] = __floats2half2_rn(xv0.x, xv0.y);
        p0.h[1] = __floats2half2_rn(xv0.z, xv0.w);
        p1.h[0] = __floats2half2_rn(xv1.x, xv1.y);
        p1.h[1] = __floats2half2_rn(xv1.z, xv1.w);
        *(uint2*)(xo0 + d) = p0.u;
        *(uint2*)(xo1 + d) = p1.u;
        #pragma unroll
        for (int e = 0; e < 8; e++) {
            float4 w = *(const float4*)&swg[e * D + d];
            a0[e] = fmaf(xv0.x, w.x, a0[e]);
            a0[e] = fmaf(xv0.y, w.y, a0[e]);
            a0[e] = fmaf(xv0.z, w.z, a0[e]);
            a0[e] = fmaf(xv0.w, w.w, a0[e]);
            a1[e] = fmaf(xv1.x, w.x, a1[e]);
            a1[e] = fmaf(xv1.y, w.y, a1[e]);
            a1[e] = fmaf(xv1.z, w.z, a1[e]);
            a1[e] = fmaf(xv1.w, w.w, a1[e]);
        }
    }
    #pragma unroll
    for (int ee = 0; ee < 8; ee++) {
        #pragma unroll
        for (int o = 16; o; o >>= 1) {
            a0[ee] += __shfl_xor_sync(0xffffffffu, a0[ee], o);
            a1[ee] += __shfl_xor_sync(0xffffffffu, a1[ee], o);
        }
    }
    if (lane == 0) {
        #pragma unroll
        for (int tk = 0; tk < 2; tk++) {
            const float* acc = tk ? a1 : a0;
            const int tok = tok0 + tk;
            int i0 = 0; float v0 = acc[0];
            #pragma unroll
            for (int ee = 1; ee < 8; ee++)
                if (acc[ee] > v0) { v0 = acc[ee]; i0 = ee; }
            int i1 = -1; float v1 = -INFINITY;
            #pragma unroll
            for (int ee = 0; ee < 8; ee++)
                if (ee != i0 && acc[ee] > v1) { v1 = acc[ee]; i1 = ee; }
            float w0 = 1.f / (1.f + expf(v1 - v0));
            g_eid[tok]     = i0;
            g_eid[S + tok] = i1;
            g_wgt[tok]     = w0;
            g_wgt[S + tok] = 1.f - w0;
        }
    }
}

// ---------------- K2: capacity-aware slot assignment (one block) -------
__global__ void k_assign() {
    __shared__ int hist[1024][8];
    const int t = threadIdx.x;
    for (int i = t; i < E * CAP; i += 1024) g_src[i] = -1;
    int h[8] = {0, 0, 0, 0, 0, 0, 0, 0};
    const int base = t * 16;
    #pragma unroll
    for (int j = 0; j < 16; j++) h[g_eid[base + j]]++;
    #pragma unroll
    for (int ee = 0; ee < 8; ee++) hist[t][ee] = h[ee];
    __syncthreads();
    const int wid = t >> 5, lane = t & 31;
    if (wid < 8) {
        int p = 0;
        #pragma unroll
        for (int j = 0; j < 32; j++) p += hist[lane * 32 + j][wid];
        int ex = p;
        #pragma unroll
        for (int o = 1; o < 32; o <<= 1) {
            int v = __shfl_up_sync(0xffffffffu, ex, o);
            if (lane >= o) ex += v;
        }
        ex -= p;  // exclusive
        int run = ex;
        #pragma unroll
        for (int j = 0; j < 32; j++) {
            int v = hist[lane * 32 + j][wid];
            hist[lane * 32 + j][wid] = run;
            run += v;
        }
    }
    __syncthreads();
    int cnt[8];
    #pragma unroll
    for (int ee = 0; ee < 8; ee++) cnt[ee] = hist[t][ee];
    #pragma unroll
    for (int j = 0; j < 16; j++) {
        int n = base + j;
        int e = g_eid[n];
        int loc = cnt[e]++;
        if (loc < CAP) {
            g_src[e * CAP + loc] = n & (S - 1);
            g_tokslot[n] = e * CAP + loc;
        } else {
            g_tokslot[n] = -1;
        }
    }
}

// ---------------- K3: fp16 HMMA expert GEMM + fused epilogue ------------
// grid = (H/128, CAP/128, E). CTA 128x128, warp 64x32, 3 stages x 32 KB,
// 2 CTAs/SM. A rows are gathered IN the loader: per-thread row pointers
// into g_xh resolved once via g_src (empty slot -> zero row g_xh[S]).
__global__ void __launch_bounds__(256, 2)
k_ffn_mma(const float* __restrict__ b1) {
    extern __shared__ char smem[];
    const uint32_t sA = s2u(smem);
    const uint32_t sB = sA + STAGES * ASTAGE;
    const int e  = blockIdx.z;
    const int m0 = blockIdx.y * MT;
    const int n0 = blockIdx.x * NTT;
    const int t  = threadIdx.x;
    const int lane = t & 31;
    const int wid  = t >> 5;
    const int warpM = wid >> 2;       // 0..1  (64 rows each)
    const int warpN = wid & 3;        // 0..3  (32 cols each)

    const char* pB = (const char*)(g_w1h + ((size_t)e * H + n0) * D);
    const size_t RS = (size_t)D * 2;  // 4096 B global row stride

    // A row pointers: fixed per thread across all K iterations.
    const int arow = t >> 3;           // base row, +32j
    const int ac   = (t & 7) * 16;     // 16-B chunk within the 128-B row
    const char* aPtr[4];
    uint32_t aSo[4];
    #pragma unroll
    for (int j = 0; j < 4; j++) {
        int r = arow + 32 * j;
        int stok = g_src[e * CAP + m0 + r];
        aPtr[j] = (const char*)(g_xh + (size_t)(stok < 0 ? S : stok) * D);
        aSo[j]  = swz128((uint32_t)(r * 128 + ac));
    }

    auto load_stage = [&](int st, int buf) {
        const size_t kb = (size_t)st * (KTILE * 2);
        #pragma unroll
        for (int j = 0; j < 4; j++)
            cpa16(sA + buf * ASTAGE + aSo[j], aPtr[j] + kb + ac);
        #pragma unroll
        for (int j = 0; j < 4; j++) {
            int idx = t + 256 * j;
            int row = idx >> 3, c = idx & 7;
            uint32_t so = swz128((uint32_t)(row * 128 + c * 16));
            cpa16(sB + buf * BSTAGE + so, pB + (size_t)row * RS + kb + c * 16);
        }
    };

    float acc[4][4][4];
    #pragma unroll
    for (int i = 0; i < 4; i++)
        #pragma unroll
        for (int j = 0; j < 4; j++)
            #pragma unroll
            for (int q = 0; q < 4; q++) acc[i][j][q] = 0.f;

    // ldmatrix per-lane base offsets (unswizzled, 128-B rows)
    const uint32_t aBase = (uint32_t)((warpM * 64 + (lane & 15)) * 128 +
                                      ((lane >> 4) << 4));
    const int brow = warpN * 32 + (lane & 7) + ((lane & 16) >> 1);
    const uint32_t bBase = (uint32_t)(brow * 128 + ((lane & 8) << 1));

    // prologue: stages 0..STAGES-2
    #pragma unroll
    for (int st = 0; st < STAGES - 1; st++) {
        load_stage(st, st);
        cp_commit();
    }

    #pragma unroll 1
    for (int it = 0; it < NK; it++) {
        cp_wait<STAGES - 2>();
        __syncthreads();
        if (it + STAGES - 1 < NK) {
            int st = it + STAGES - 1;
            load_stage(st, st % STAGES);
        }
        cp_commit();

        const int buf = it % STAGES;
        const uint32_t abuf = sA + buf * ASTAGE;
        const uint32_t bbuf = sB + buf * BSTAGE;
        #pragma unroll
        for (int s = 0; s < 4; s++) {
            uint32_t a[4][4], b[2][4];
            #pragma unroll
            for (int mt = 0; mt < 4; mt++)
                ldsm4(a[mt], abuf + swz128(aBase + mt * 2048 + s * 32));
            #pragma unroll
            for (int np = 0; np < 2; np++)
                ldsm4(b[np], bbuf + swz128(bBase + np * 2048 + s * 32));
            #pragma unroll
            for (int mt = 0; mt < 4; mt++)
                #pragma unroll
                for (int nt = 0; nt < 4; nt++) {
                    const int np = nt >> 1, o = (nt & 1) * 2;
                    mma16816(acc[mt][nt], a[mt], b[np][o], b[np][o + 1]);
                }
        }
    }

    // ---- epilogue: relu(acc + b1) . w2sum, reduce over 128 N ----
    __syncthreads();                       // all loads retired; reuse smem
    float* red = (float*)smem;             // [128][4]
    const int g  = lane >> 2;
    const int t4 = lane & 3;
    const float* b1p = b1 + (size_t)e * H + n0;
    const float* wp  = g_w2sum + (size_t)e * H + n0;
    #pragma unroll
    for (int mt = 0; mt < 4; mt++) {
        float sAcc = 0.f, sBcc = 0.f;
        #pragma unroll
        for (int nt = 0; nt < 4; nt++) {
            int ni = warpN * 32 + nt * 8 + t4 * 2;
            float bb0 = __ldg(b1p + ni),     ww0 = __ldg(wp + ni);
            float bb1 = __ldg(b1p + ni + 1), ww1 = __ldg(wp + ni + 1);
            sAcc += fmaxf(acc[mt][nt][0] + bb0, 0.f) * ww0 +
                    fmaxf(acc[mt][nt][1] + bb1, 0.f) * ww1;
            sBcc += fmaxf(acc[mt][nt][2] + bb0, 0.f) * ww0 +
                    fmaxf(acc[mt][nt][3] + bb1, 0.f) * ww1;
        }
        sAcc += __shfl_xor_sync(0xffffffffu, sAcc, 1);
        sAcc += __shfl_xor_sync(0xffffffffu, sAcc, 2);
        sBcc += __shfl_xor_sync(0xffffffffu, sBcc, 1);
        sBcc += __shfl_xor_sync(0xffffffffu, sBcc, 2);
        if (t4 == 0) {
            int r = warpM * 64 + mt * 16 + g;
            red[r * 4 + warpN]       = sAcc;
            red[(r + 8) * 4 + warpN] = sBcc;
        }
    }
    __syncthreads();
    if (t < 128) {
        float v = red[t * 4] + red[t * 4 + 1] + red[t * 4 + 2] + red[t * 4 + 3];
        g_part[(size_t)(e * CAP + m0 + t) * NTILES + blockIdx.x] = v;
    }
}

// ---------------- K4: fused combine + log_softmax -----------------------
// grid = B, 1024 threads; thread t handles tokens t and t+1024 of its row.
__global__ void k_out(float* __restrict__ out) {
    __shared__ float sh[1024];
    const int b = blockIdx.x;
    const int t = threadIdx.x;
    float v[2];
    #pragma unroll
    for (int half = 0; half < 2; half++) {
        const int s = b * T + t + half * 1024;
        float l = 0.f;
        #pragma unroll
        for (int k = 0; k < KK; k++) {
            int slot = g_tokslot[k * S + s];
            if (slot >= 0) {
                const float4* p = (const float4*)(g_part + (size_t)slot * NTILES);
                float4 c0 = p[0], c1 = p[1], c2 = p[2], c3 = p[3];
                float c = c0.x + c0.y + c0.z + c0.w + c1.x + c1.y + c1.z + c1.w +
                          c2.x + c2.y + c2.z + c2.w + c3.x + c3.y + c3.z + c3.w;
                l += g_wgt[k * S + s] * (c + g_b2sum[g_eid[k * S + s]]);
            }
        }
        v[half] = l;
    }
    sh[t] = fmaxf(v[0], v[1]);
    __syncthreads();
    for (int o = 512; o; o >>= 1) {
        if (t < o) sh[t] = fmaxf(sh[t], sh[t + o]);
        __syncthreads();
    }
    const float mx = sh[0];
    __syncthreads();
    sh[t] = expf(v[0] - mx) + expf(v[1] - mx);
    __syncthreads();
    for (int o = 512; o; o >>= 1) {
        if (t < o) sh[t] += sh[t + o];
        __syncthreads();
    }
    const float lse = logf(sh[0]) + mx;
    out[(size_t)b * T + t]        = v[0] - lse;
    out[(size_t)b * T + t + 1024] = v[1] - lse;
}

// ---------------- launch ------------------------------------------------
extern "C" void kernel_launch(void* const* d_in, const int* in_sizes, int n_in,
                              void* d_out, int out_size) {
    const float* x  = (const float*)d_in[0];   // [B,T,D]
    const float* wg = (const float*)d_in[1];   // [D,E]
    const float* w1 = (const float*)d_in[2];   // [E,D,H]
    const float* b1 = (const float*)d_in[3];   // [E,H]
    const float* w2 = (const float*)d_in[4];   // [E,H,D]
    const float* b2 = (const float*)d_in[5];   // [E,D]
    float* out = (float*)d_out;                // [B,T]
    (void)in_sizes; (void)n_in; (void)out_size;

    cudaFuncSetAttribute(k_ffn_mma,
                         cudaFuncAttributeMaxDynamicSharedMemorySize, SMEM_FFN);
    cudaFuncSetAttribute(k_gate,
                         cudaFuncAttributeMaxDynamicSharedMemorySize, D * E * 4);

    // fork: weight prep on the side stream, overlapped with token branch
    cudaEventRecord(g_ev_fork, 0);
    cudaStreamWaitEvent(g_side_stream, g_ev_fork, 0);
    k_prep<<<PREP_TOT, 256, 0, g_side_stream>>>(w1, w2, b2);
    cudaEventRecord(g_ev_join, g_side_stream);

    // token branch on the main stream (gather is folded into gate + GEMM)
    k_gate<<<S / 32, 512, D * E * 4>>>(x, wg);
    k_assign<<<1, 1024>>>();

    // join: GEMM needs both branches
    cudaStreamWaitEvent(0, g_ev_join, 0);
    k_ffn_mma<<<dim3(H / NTT, CAP / MT, E), 256, SMEM_FFN>>>(b1);

    // fused combine + log_softmax
    k_out<<<B, 1024>>>(out);
}